// round 7
// baseline (speedup 1.0000x reference)
#include <cuda_runtime.h>
#include <math.h>

// SE(3) exp + point transform, single kernel, NO block barrier.
// out[bt,n,:] = R(dofs[bt]) * X[bt,n,:] + t(dofs[bt])
// X_v: [B,T,N,3] f32, dofs: [B,T,6] f32, out: [B,T,N,3] f32. B=64,T=28,N=4096.
//
// Lane 0 of each warp computes R,t; broadcast with __shfl_sync. Warps run
// fully independently (no __syncthreads). Each thread streams 8 points
// (6 float4 loads in flight -> MLP=6) to amortize the per-warp prologue.

#define THREADS 256
#define PTS_PER_THREAD 8            // 8 points = 24 floats = 6 float4

__global__ void __launch_bounds__(THREADS)
se3_transform_kernel(const float* __restrict__ X,
                     const float* __restrict__ dofs,
                     float* __restrict__ out)
{
    // Flat tile index (1 tile = 8 points = 24 floats). 512 tiles per bt
    // slice; a warp spans 32 consecutive tiles (256 points) -> all lanes of
    // a warp share the same bt (512 % 32 == 0).
    const unsigned tile = blockIdx.x * THREADS + threadIdx.x;
    const unsigned bt   = tile >> 9;             // tile / 512
    const int lane      = threadIdx.x & 31;

    const size_t base = (size_t)tile * 24;       // float offset
    const float4* __restrict__ src = reinterpret_cast<const float4*>(X + base);
    float4* __restrict__ dst = reinterpret_cast<float4*>(out + base);

    // ---- issue all 6 data loads FIRST (independent of R,t) ----
    const float4 va = __ldcs(&src[0]);
    const float4 vb = __ldcs(&src[1]);
    const float4 vc = __ldcs(&src[2]);
    const float4 vd = __ldcs(&src[3]);
    const float4 ve = __ldcs(&src[4]);
    const float4 vf = __ldcs(&src[5]);

    // ---- lane 0 computes R,t (hidden under load latency) ----
    float r00, r01, r02, r10, r11, r12, r20, r21, r22, t0, t1, t2;
    if (lane == 0) {
        const float* d = dofs + bt * 6;
        const float tx = __ldg(&d[0]), ty = __ldg(&d[1]), tz = __ldg(&d[2]);
        const float wx = __ldg(&d[3]), wy = __ldg(&d[4]), wz = __ldg(&d[5]);

        const float nrm   = wx*wx + wy*wy + wz*wz;
        const float th2c  = fmaxf(nrm, 1.0e-4f);   // clip BEFORE sqrt (matches ref)
        const float theta = sqrtf(th2c);
        float st, ct;
        sincosf(theta, &st, &ct);
        const float inv_t  = 1.0f / theta;
        const float inv_t2 = inv_t * inv_t;
        const float f1 = st * inv_t;
        const float f2 = (1.0f - ct) * inv_t2;
        const float f3 = (theta - st) * inv_t2 * inv_t;

        // H2 = H@H = w w^T - (w.w) I  (raw nrm, matches ref)
        const float h2xx = wx*wx - nrm, h2yy = wy*wy - nrm, h2zz = wz*wz - nrm;
        const float h2xy = wx*wy, h2xz = wx*wz, h2yz = wy*wz;

        r00 = 1.0f + f2*h2xx;
        r01 = -f1*wz + f2*h2xy;
        r02 =  f1*wy + f2*h2xz;
        r10 =  f1*wz + f2*h2xy;
        r11 = 1.0f + f2*h2yy;
        r12 = -f1*wx + f2*h2yz;
        r20 = -f1*wy + f2*h2xz;
        r21 =  f1*wx + f2*h2yz;
        r22 = 1.0f + f2*h2zz;

        const float v00 = 1.0f + f3*h2xx;
        const float v01 = -f2*wz + f3*h2xy;
        const float v02 =  f2*wy + f3*h2xz;
        const float v10 =  f2*wz + f3*h2xy;
        const float v11 = 1.0f + f3*h2yy;
        const float v12 = -f2*wx + f3*h2yz;
        const float v20 = -f2*wy + f3*h2xz;
        const float v21 =  f2*wx + f3*h2yz;
        const float v22 = 1.0f + f3*h2zz;

        t0 = v00*tx + v01*ty + v02*tz;
        t1 = v10*tx + v11*ty + v12*tz;
        t2 = v20*tx + v21*ty + v22*tz;
    }

    // ---- warp broadcast (no smem, no block barrier) ----
    r00 = __shfl_sync(0xffffffffu, r00, 0);
    r01 = __shfl_sync(0xffffffffu, r01, 0);
    r02 = __shfl_sync(0xffffffffu, r02, 0);
    r10 = __shfl_sync(0xffffffffu, r10, 0);
    r11 = __shfl_sync(0xffffffffu, r11, 0);
    r12 = __shfl_sync(0xffffffffu, r12, 0);
    r20 = __shfl_sync(0xffffffffu, r20, 0);
    r21 = __shfl_sync(0xffffffffu, r21, 0);
    r22 = __shfl_sync(0xffffffffu, r22, 0);
    t0  = __shfl_sync(0xffffffffu, t0, 0);
    t1  = __shfl_sync(0xffffffffu, t1, 0);
    t2  = __shfl_sync(0xffffffffu, t2, 0);

#define XFX(px, py, pz) fmaf(r00, (px), fmaf(r01, (py), fmaf(r02, (pz), t0)))
#define XFY(px, py, pz) fmaf(r10, (px), fmaf(r11, (py), fmaf(r12, (pz), t1)))
#define XFZ(px, py, pz) fmaf(r20, (px), fmaf(r21, (py), fmaf(r22, (pz), t2)))

    // points 0..3 (va,vb,vc)
    const float o0x = XFX(va.x, va.y, va.z), o0y = XFY(va.x, va.y, va.z), o0z = XFZ(va.x, va.y, va.z);
    const float o1x = XFX(va.w, vb.x, vb.y), o1y = XFY(va.w, vb.x, vb.y), o1z = XFZ(va.w, vb.x, vb.y);
    const float o2x = XFX(vb.z, vb.w, vc.x), o2y = XFY(vb.z, vb.w, vc.x), o2z = XFZ(vb.z, vb.w, vc.x);
    const float o3x = XFX(vc.y, vc.z, vc.w), o3y = XFY(vc.y, vc.z, vc.w), o3z = XFZ(vc.y, vc.z, vc.w);

    __stcs(&dst[0], make_float4(o0x, o0y, o0z, o1x));
    __stcs(&dst[1], make_float4(o1y, o1z, o2x, o2y));
    __stcs(&dst[2], make_float4(o2z, o3x, o3y, o3z));

    // points 4..7 (vd,ve,vf)
    const float o4x = XFX(vd.x, vd.y, vd.z), o4y = XFY(vd.x, vd.y, vd.z), o4z = XFZ(vd.x, vd.y, vd.z);
    const float o5x = XFX(vd.w, ve.x, ve.y), o5y = XFY(vd.w, ve.x, ve.y), o5z = XFZ(vd.w, ve.x, ve.y);
    const float o6x = XFX(ve.z, ve.w, vf.x), o6y = XFY(ve.z, ve.w, vf.x), o6z = XFZ(ve.z, ve.w, vf.x);
    const float o7x = XFX(vf.y, vf.z, vf.w), o7y = XFY(vf.y, vf.z, vf.w), o7z = XFZ(vf.y, vf.z, vf.w);

    __stcs(&dst[3], make_float4(o4x, o4y, o4z, o5x));
    __stcs(&dst[4], make_float4(o5y, o5z, o6x, o6y));
    __stcs(&dst[5], make_float4(o6z, o7x, o7y, o7z));

#undef XFX
#undef XFY
#undef XFZ
}

extern "C" void kernel_launch(void* const* d_in, const int* in_sizes, int n_in,
                              void* d_out, int out_size)
{
    const float* X    = (const float*)d_in[0];   // [B,T,N,3]
    const float* dofs = (const float*)d_in[1];   // [B,T,6]

    const int nBT = in_sizes[1] / 6;             // 1792
    const int N   = (in_sizes[0] / nBT) / 3;     // 4096

    const int totalTiles = nBT * (N / PTS_PER_THREAD);   // 1792 * 512
    const int blocks = totalTiles / THREADS;             // 3584

    se3_transform_kernel<<<blocks, THREADS>>>(X, dofs, (float*)d_out);
}

// round 8
// speedup vs baseline: 1.1383x; 1.1383x over previous
#include <cuda_runtime.h>
#include <math.h>

// SE(3) exp + point transform, single kernel, NO block barrier.
// out[bt,n,:] = R(dofs[bt]) * X[bt,n,:] + t(dofs[bt])
// X_v: [B,T,N,3] f32, dofs: [B,T,6] f32, out: [B,T,N,3] f32. B=64,T=28,N=4096.
//
// Lane 0 of each warp computes R,t once; broadcast via __shfl_sync.
// Each thread then runs ITERS sequential iterations of (3x float4 load ->
// 9 FMA/pt -> 3x float4 store). #pragma unroll 1 keeps each iteration's
// load batch at MLP_p1=3 (empirically the sweet spot: MLP_p1=6 variants
// collapse DRAM% from 58 to 47 via cross-CTA L1tex-queue contention).

#define THREADS 256
#define ITERS 2                 // iterations per thread, 4 pts each
#define TILES_PER_SLICE 1024    // N*3/12

__global__ void __launch_bounds__(THREADS)
se3_transform_kernel(const float* __restrict__ X,
                     const float* __restrict__ dofs,
                     float* __restrict__ out)
{
    // Block covers ITERS*THREADS = 512 consecutive tiles = half a bt slice.
    const unsigned bt   = blockIdx.x >> 1;
    const unsigned half = blockIdx.x & 1;
    const int lane      = threadIdx.x & 31;

    const unsigned tile0 = bt * TILES_PER_SLICE + half * (ITERS * THREADS) + threadIdx.x;

    // ---- warm the pipeline: issue iteration-0 loads FIRST ----
    const float4* __restrict__ src0 =
        reinterpret_cast<const float4*>(X + (size_t)tile0 * 12);
    float4 va = __ldcs(&src0[0]);
    float4 vb = __ldcs(&src0[1]);
    float4 vc = __ldcs(&src0[2]);

    // ---- lane 0 computes R,t (hidden under load latency) ----
    float r00, r01, r02, r10, r11, r12, r20, r21, r22, t0, t1, t2;
    if (lane == 0) {
        const float* d = dofs + bt * 6;
        const float tx = __ldg(&d[0]), ty = __ldg(&d[1]), tz = __ldg(&d[2]);
        const float wx = __ldg(&d[3]), wy = __ldg(&d[4]), wz = __ldg(&d[5]);

        const float nrm   = wx*wx + wy*wy + wz*wz;
        const float th2c  = fmaxf(nrm, 1.0e-4f);   // clip BEFORE sqrt (matches ref)
        const float theta = sqrtf(th2c);
        float st, ct;
        sincosf(theta, &st, &ct);
        const float inv_t  = 1.0f / theta;
        const float inv_t2 = inv_t * inv_t;
        const float f1 = st * inv_t;
        const float f2 = (1.0f - ct) * inv_t2;
        const float f3 = (theta - st) * inv_t2 * inv_t;

        // H2 = H@H = w w^T - (w.w) I  (raw nrm, matches ref)
        const float h2xx = wx*wx - nrm, h2yy = wy*wy - nrm, h2zz = wz*wz - nrm;
        const float h2xy = wx*wy, h2xz = wx*wz, h2yz = wy*wz;

        r00 = 1.0f + f2*h2xx;
        r01 = -f1*wz + f2*h2xy;
        r02 =  f1*wy + f2*h2xz;
        r10 =  f1*wz + f2*h2xy;
        r11 = 1.0f + f2*h2yy;
        r12 = -f1*wx + f2*h2yz;
        r20 = -f1*wy + f2*h2xz;
        r21 =  f1*wx + f2*h2yz;
        r22 = 1.0f + f2*h2zz;

        const float v00 = 1.0f + f3*h2xx;
        const float v01 = -f2*wz + f3*h2xy;
        const float v02 =  f2*wy + f3*h2xz;
        const float v10 =  f2*wz + f3*h2xy;
        const float v11 = 1.0f + f3*h2yy;
        const float v12 = -f2*wx + f3*h2yz;
        const float v20 = -f2*wy + f3*h2xz;
        const float v21 =  f2*wx + f3*h2yz;
        const float v22 = 1.0f + f3*h2zz;

        t0 = v00*tx + v01*ty + v02*tz;
        t1 = v10*tx + v11*ty + v12*tz;
        t2 = v20*tx + v21*ty + v22*tz;
    }

    // ---- warp broadcast (no smem, no block barrier) ----
    r00 = __shfl_sync(0xffffffffu, r00, 0);
    r01 = __shfl_sync(0xffffffffu, r01, 0);
    r02 = __shfl_sync(0xffffffffu, r02, 0);
    r10 = __shfl_sync(0xffffffffu, r10, 0);
    r11 = __shfl_sync(0xffffffffu, r11, 0);
    r12 = __shfl_sync(0xffffffffu, r12, 0);
    r20 = __shfl_sync(0xffffffffu, r20, 0);
    r21 = __shfl_sync(0xffffffffu, r21, 0);
    r22 = __shfl_sync(0xffffffffu, r22, 0);
    t0  = __shfl_sync(0xffffffffu, t0, 0);
    t1  = __shfl_sync(0xffffffffu, t1, 0);
    t2  = __shfl_sync(0xffffffffu, t2, 0);

#pragma unroll 1
    for (int it = 0; it < ITERS; ++it) {
        const unsigned tile = tile0 + it * THREADS;
        float4* __restrict__ dst =
            reinterpret_cast<float4*>(out + (size_t)tile * 12);

        // transform 4 points packed in va,vb,vc
        const float o0x = fmaf(r00, va.x, fmaf(r01, va.y, fmaf(r02, va.z, t0)));
        const float o0y = fmaf(r10, va.x, fmaf(r11, va.y, fmaf(r12, va.z, t1)));
        const float o0z = fmaf(r20, va.x, fmaf(r21, va.y, fmaf(r22, va.z, t2)));

        const float o1x = fmaf(r00, va.w, fmaf(r01, vb.x, fmaf(r02, vb.y, t0)));
        const float o1y = fmaf(r10, va.w, fmaf(r11, vb.x, fmaf(r12, vb.y, t1)));
        const float o1z = fmaf(r20, va.w, fmaf(r21, vb.x, fmaf(r22, vb.y, t2)));

        const float o2x = fmaf(r00, vb.z, fmaf(r01, vb.w, fmaf(r02, vc.x, t0)));
        const float o2y = fmaf(r10, vb.z, fmaf(r11, vb.w, fmaf(r12, vc.x, t1)));
        const float o2z = fmaf(r20, vb.z, fmaf(r21, vb.w, fmaf(r22, vc.x, t2)));

        const float o3x = fmaf(r00, vc.y, fmaf(r01, vc.z, fmaf(r02, vc.w, t0)));
        const float o3y = fmaf(r10, vc.y, fmaf(r11, vc.z, fmaf(r12, vc.w, t1)));
        const float o3z = fmaf(r20, vc.y, fmaf(r21, vc.z, fmaf(r22, vc.w, t2)));

        // prefetch next iteration's 3 loads before the stores
        if (it + 1 < ITERS) {
            const float4* __restrict__ srcN =
                reinterpret_cast<const float4*>(X + (size_t)(tile + THREADS) * 12);
            const float4 na = __ldcs(&srcN[0]);
            const float4 nb = __ldcs(&srcN[1]);
            const float4 nc = __ldcs(&srcN[2]);

            __stcs(&dst[0], make_float4(o0x, o0y, o0z, o1x));
            __stcs(&dst[1], make_float4(o1y, o1z, o2x, o2y));
            __stcs(&dst[2], make_float4(o2z, o3x, o3y, o3z));

            va = na; vb = nb; vc = nc;
        } else {
            __stcs(&dst[0], make_float4(o0x, o0y, o0z, o1x));
            __stcs(&dst[1], make_float4(o1y, o1z, o2x, o2y));
            __stcs(&dst[2], make_float4(o2z, o3x, o3y, o3z));
        }
    }
}

extern "C" void kernel_launch(void* const* d_in, const int* in_sizes, int n_in,
                              void* d_out, int out_size)
{
    const float* X    = (const float*)d_in[0];   // [B,T,N,3]
    const float* dofs = (const float*)d_in[1];   // [B,T,6]

    const int nBT = in_sizes[1] / 6;             // 1792
    const int N   = (in_sizes[0] / nBT) / 3;     // 4096

    const int tilesPerBlock = ITERS * THREADS;                    // 512
    const int blocks = nBT * (N * 3 / 12) / tilesPerBlock;        // 3584

    se3_transform_kernel<<<blocks, THREADS>>>(X, dofs, (float*)d_out);
}